// round 6
// baseline (speedup 1.0000x reference)
#include <cuda_runtime.h>

#define NBLK 2048
#define NTHR 256

// Per-block partials, SoA layout: [6][NBLK]. __device__ global (no allocation).
__device__ float g_part[6 * NBLK];

__device__ __forceinline__ void warpRed(float& a) {
    #pragma unroll
    for (int o = 16; o; o >>= 1) a += __shfl_down_sync(0xffffffffu, a, o);
}

__device__ __forceinline__ void sample_accum(
    float x0, float x1, float x2, int t,
    const float* sW, const float* sP,
    float& s_wce, float& s_w, float& s_foc, float& s_saf,
    int& n_crit, int& n_miss)
{
    // argmax (first-max wins, matching jnp.argmax)
    int pred = 0; float best = x0;
    if (x1 > best) { best = x1; pred = 1; }
    if (x2 > best) { best = x2; pred = 2; }
    // stable log-sum-exp (max = best)
    float e0 = __expf(x0 - best), e1 = __expf(x1 - best), e2 = __expf(x2 - best);
    float lse = best + __logf(e0 + e1 + e2);
    float xt = (t == 0) ? x0 : ((t == 1) ? x1 : x2);
    float ce = lse - xt;
    float w = sW[t];
    s_wce = fmaf(w, ce, s_wce);
    s_w += w;
    float pt = __expf(-ce);
    float om = 1.0f - pt;
    s_foc = fmaf(om * om, ce, s_foc);   // ALPHA applied at the end
    s_saf += sP[t * 3 + pred];
    bool crit = (t == 2);
    n_crit += crit ? 1 : 0;
    n_miss += (crit && pred != 2) ? 1 : 0;
}

__global__ __launch_bounds__(NTHR) void loss_main(
    const float* __restrict__ outputs,
    const int* __restrict__ targets,    // harness maps int64 -> int32
    const float* __restrict__ cw,
    const float* __restrict__ pm,
    int num_groups, int B)
{
    __shared__ float sW[3], sP[9];
    if (threadIdx.x < 3) sW[threadIdx.x] = cw[threadIdx.x];
    if (threadIdx.x < 9) sP[threadIdx.x] = pm[threadIdx.x];
    __syncthreads();

    const float4* __restrict__ o4 = (const float4*)outputs;
    const int4*   __restrict__ t4 = (const int4*)targets;

    float s_wce = 0.f, s_w = 0.f, s_foc = 0.f, s_saf = 0.f;
    int n_crit = 0, n_miss = 0;

    const int stride = gridDim.x * NTHR;
    for (int g = blockIdx.x * NTHR + threadIdx.x; g < num_groups; g += stride) {
        // 4 samples per group: 3x float4 logits (48B) + 1x int4 targets (16B).
        // All loads front-batched for MLP.
        long long go = 3 * (long long)g;
        float4 a = __ldcs(o4 + go + 0);
        float4 b = __ldcs(o4 + go + 1);
        float4 c = __ldcs(o4 + go + 2);
        int4   t = __ldcs(t4 + g);

        float xs[12] = {a.x, a.y, a.z, a.w, b.x, b.y, b.z, b.w, c.x, c.y, c.z, c.w};
        int   ts[4]  = {t.x, t.y, t.z, t.w};
        #pragma unroll
        for (int i = 0; i < 4; i++) {
            sample_accum(xs[3*i+0], xs[3*i+1], xs[3*i+2], ts[i],
                         sW, sP, s_wce, s_w, s_foc, s_saf, n_crit, n_miss);
        }
    }

    // Tail samples (B not divisible by 4) — handled scalar by block 0's low threads.
    int tail = B - num_groups * 4;
    if (blockIdx.x == 0 && (int)threadIdx.x < tail) {
        long long idx = (long long)num_groups * 4 + threadIdx.x;
        float x0 = outputs[3 * idx + 0];
        float x1 = outputs[3 * idx + 1];
        float x2 = outputs[3 * idx + 2];
        int t = targets[idx];
        sample_accum(x0, x1, x2, t, sW, sP, s_wce, s_w, s_foc, s_saf, n_crit, n_miss);
    }

    float f_crit = (float)n_crit, f_miss = (float)n_miss;
    warpRed(s_wce); warpRed(s_w); warpRed(s_foc);
    warpRed(s_saf); warpRed(f_crit); warpRed(f_miss);

    __shared__ float red[6][NTHR / 32];
    int warp = threadIdx.x >> 5, lane = threadIdx.x & 31;
    if (lane == 0) {
        red[0][warp] = s_wce; red[1][warp] = s_w;    red[2][warp] = s_foc;
        red[3][warp] = s_saf; red[4][warp] = f_crit; red[5][warp] = f_miss;
    }
    __syncthreads();
    if (threadIdx.x < 32) {
        const int nw = NTHR / 32;
        #pragma unroll
        for (int k = 0; k < 6; k++) {
            float v = (lane < nw) ? red[k][lane] : 0.f;
            #pragma unroll
            for (int o = nw / 2; o; o >>= 1) v += __shfl_down_sync(0xffffffffu, v, o);
            if (lane == 0) g_part[k * NBLK + blockIdx.x] = v;
        }
    }
}

__global__ __launch_bounds__(NTHR) void loss_final(float* out, float invB)
{
    float acc[6] = {0, 0, 0, 0, 0, 0};
    for (int i = threadIdx.x; i < NBLK; i += NTHR) {
        #pragma unroll
        for (int k = 0; k < 6; k++) acc[k] += g_part[k * NBLK + i];
    }
    #pragma unroll
    for (int k = 0; k < 6; k++) warpRed(acc[k]);

    __shared__ float red[6][NTHR / 32];
    int warp = threadIdx.x >> 5, lane = threadIdx.x & 31;
    if (lane == 0) {
        #pragma unroll
        for (int k = 0; k < 6; k++) red[k][warp] = acc[k];
    }
    __syncthreads();
    if (threadIdx.x == 0) {
        float s[6];
        #pragma unroll
        for (int k = 0; k < 6; k++) {
            float v = 0.f;
            #pragma unroll
            for (int w = 0; w < NTHR / 32; w++) v += red[k][w];
            s[k] = v;
        }
        float ce_loss = s[0] / s[1];
        float focal   = 0.25f * s[2] * invB;       // ALPHA = 0.25
        float safety  = s[3] * invB;
        float crit    = (s[4] > 0.f) ? (s[5] / s[4]) * 50.0f : 0.f;
        out[0] = ce_loss + 0.3f * focal + 0.4f * safety + 0.6f * crit;
    }
}

extern "C" void kernel_launch(void* const* d_in, const int* in_sizes, int n_in,
                              void* d_out, int out_size) {
    const float* outputs = (const float*)d_in[0];
    const int*   targets = (const int*)d_in[1];     // int64 downcast to int32 by harness
    const float* cw      = (const float*)d_in[2];
    const float* pm      = (const float*)d_in[3];
    int B = in_sizes[1];             // targets element count
    int num_groups = B / 4;
    loss_main<<<NBLK, NTHR>>>(outputs, targets, cw, pm, num_groups, B);
    loss_final<<<1, NTHR>>>((float*)d_out, 1.0f / (float)B);
}